// round 14
// baseline (speedup 1.0000x reference)
#include <cuda_runtime.h>

#define NCOLS            696     // 16 + 120 + 560
#define NQ_TOTAL         174     // NCOLS / 4
#define ROWS_PER_BLOCK   32      // one tile per block
#define THREADS          64      // warp 0 = producer, warp 1 = consumer
#define MIN_BLOCKS       6       // 6 blocks/SM -> 12 warps, 6 independent pipelines
#define ROW_STRIDE       68      // 64 data words + 4 pad (conflict-free STS.128 & LDS.128)
#define BUF_FLOATS       (ROWS_PER_BLOCK * ROW_STRIDE)  // 2176 floats = 8704 B
#define PERSIST_ROWS     28672   // 28672 * 2784 B = 79.8 MB pinned in L2 (of 126 MB)

// Named-barrier producer/consumer protocol (64 threads = both warps).
#define BAR_SYNC(ID)   asm volatile("bar.sync %0, 64;"   :: "r"(ID) : "memory")
#define BAR_ARRIVE(ID) asm volatile("bar.arrive %0, 64;" :: "r"(ID) : "memory")
#define FULL0 1
#define FULL1 2
#define FULL2 3
#define FREE0 4
#define FREE1 5
#define FREE2 6

// Dubois t-norm for a,b >= 0:  a*b / max(max(a,b), lambda) == min(a, b, a*b/lambda)
__device__ __forceinline__ float tnorm(float a, float b, float inv_l) {
    return fminf(fminf(a, b), a * b * inv_l);
}

// Evict-last 256-bit store (ptxas requires 32B width for L2::evict_last).
// Line lingers in L2 across graph replays -> rewritten in place each
// iteration, generating no steady-state DRAM write traffic.
__device__ __forceinline__ void st_evict_last_256(float* p, float4 a, float4 b) {
    asm volatile("st.global.L2::evict_last.v8.f32 [%0], {%1,%2,%3,%4,%5,%6,%7,%8};"
                 :: "l"(p),
                    "f"(a.x), "f"(a.y), "f"(a.z), "f"(a.w),
                    "f"(b.x), "f"(b.y), "f"(b.z), "f"(b.w)
                 : "memory");
}

// Pack values for columns [LO,HI) of this lane's row into its buffer row
// using STS.128 every 4 columns. col/rel are compile-time constants.
template<int LO, int HI>
__device__ __forceinline__ void compute_chunk(const float xv[16], float inv_l,
                                              float* __restrict__ wbuf, int lane) {
    float4 acc;
    float* rowp = wbuf + lane * ROW_STRIDE;

    int col = 0;
    #define EMIT(VAL)                                                           \
        do {                                                                    \
            if (col >= LO && col < HI) {                                        \
                int rel = col - LO;                                             \
                if ((rel & 3) == 0) acc.x = (VAL);                              \
                else if ((rel & 3) == 1) acc.y = (VAL);                         \
                else if ((rel & 3) == 2) acc.z = (VAL);                         \
                else {                                                          \
                    acc.w = (VAL);                                              \
                    *reinterpret_cast<float4*>(rowp + (rel - 3)) = acc;         \
                }                                                               \
            }                                                                   \
            col++;                                                              \
        } while (0)

    #pragma unroll
    for (int i = 0; i < 16; i++) EMIT(xv[i]);                    // singles 0..15

    #pragma unroll
    for (int i = 0; i < 16; i++) {                               // pairs 16..135
        #pragma unroll
        for (int j = i + 1; j < 16; j++) EMIT(tnorm(xv[i], xv[j], inv_l));
    }

    #pragma unroll
    for (int i = 0; i < 16; i++) {                               // triples 136..695
        #pragma unroll
        for (int j = i + 1; j < 16; j++) {
            float p = tnorm(xv[i], xv[j], inv_l);                // dead if no k in range
            #pragma unroll
            for (int k = j + 1; k < 16; k++) EMIT(tnorm(p, xv[k], inv_l));
        }
    }
    #undef EMIT
}

// Streaming writeout (evict-first .cs, 128-bit) of columns [LO,HI).
template<int LO, int HI>
__device__ __forceinline__ void writeout_stream(const float* __restrict__ wbuf,
                                                float4* __restrict__ out4,
                                                int wrow0, int lane) {
    constexpr int NQ = (HI - LO) / 4;   // 16 or 14 float4s per row in this chunk
    #pragma unroll
    for (int it = 0; it < NQ; it++) {
        int idx = it * 32 + lane;
        int q = idx % NQ;
        int r = idx / NQ;
        float4 v = *reinterpret_cast<const float4*>(wbuf + r * ROW_STRIDE + 4 * q);
        __stcs(&out4[(size_t)(wrow0 + r) * NQ_TOTAL + (LO / 4) + q], v);
    }
}

// Persistent writeout (evict_last, 256-bit) of columns [LO,HI).
// All global addresses 32B-aligned: row stride 2784B = 87*32, LO*4 % 32 == 0.
template<int LO, int HI>
__device__ __forceinline__ void writeout_persist(const float* __restrict__ wbuf,
                                                 float* __restrict__ out,
                                                 int wrow0, int lane) {
    constexpr int NG = (HI - LO) / 8;   // 8 or 7 8-float groups per row
    #pragma unroll
    for (int it = 0; it < NG; it++) {
        int idx = it * 32 + lane;
        int g = idx % NG;
        int r = idx / NG;
        const float* s = wbuf + r * ROW_STRIDE + 8 * g;
        float4 v0 = *reinterpret_cast<const float4*>(s);
        float4 v1 = *reinterpret_cast<const float4*>(s + 4);
        st_evict_last_256(out + (size_t)(wrow0 + r) * NCOLS + LO + 8 * g, v0, v1);
    }
}

template<bool PERSIST>
__device__ __forceinline__ void consumer_loop(const float (*buf)[BUF_FLOATS],
                                              float* __restrict__ out,
                                              int wrow0, int lane) {
    float4* out4 = reinterpret_cast<float4*>(out);
#define CSTEP(LO, HI, FULL_B, K)                                           \
    BAR_SYNC(FULL_B);                                                      \
    if (PERSIST) writeout_persist<LO, HI>(buf[K], out,  wrow0, lane);      \
    else         writeout_stream <LO, HI>(buf[K], out4, wrow0, lane);

    CSTEP(0,   64,  FULL0, 0)  BAR_ARRIVE(FREE0);
    CSTEP(64,  128, FULL1, 1)  BAR_ARRIVE(FREE1);
    CSTEP(128, 192, FULL2, 2)  BAR_ARRIVE(FREE2);
    CSTEP(192, 256, FULL0, 0)  BAR_ARRIVE(FREE0);
    CSTEP(256, 320, FULL1, 1)  BAR_ARRIVE(FREE1);
    CSTEP(320, 384, FULL2, 2)  BAR_ARRIVE(FREE2);
    CSTEP(384, 448, FULL0, 0)  BAR_ARRIVE(FREE0);
    CSTEP(448, 512, FULL1, 1)  BAR_ARRIVE(FREE1);
    CSTEP(512, 576, FULL2, 2)
    CSTEP(576, 640, FULL0, 0)
    CSTEP(640, 696, FULL1, 1)
#undef CSTEP
}

__global__ void __launch_bounds__(THREADS, MIN_BLOCKS)
dubois_kernel(const float* __restrict__ x,
              const float* __restrict__ lambda_,
              float* __restrict__ out) {
    __shared__ float buf[3][BUF_FLOATS];   // 26,112 B: 3-deep ring

    const int lane = threadIdx.x & 31;
    const int wid  = threadIdx.x >> 5;

    const int wrow0 = blockIdx.x * ROWS_PER_BLOCK;

    if (wid == 0) {
        // ---- Producer warp ----
        const float inv_l = 1.0f / __ldg(lambda_);
        const int row = wrow0 + lane;
        float xv[16];
        const float4* xp = reinterpret_cast<const float4*>(x) + (size_t)row * 4;
        float4 a = xp[0], b = xp[1], c = xp[2], d = xp[3];
        xv[0]=a.x;  xv[1]=a.y;  xv[2]=a.z;  xv[3]=a.w;
        xv[4]=b.x;  xv[5]=b.y;  xv[6]=b.z;  xv[7]=b.w;
        xv[8]=c.x;  xv[9]=c.y;  xv[10]=c.z; xv[11]=c.w;
        xv[12]=d.x; xv[13]=d.y; xv[14]=d.z; xv[15]=d.w;

        // Chunks 0..2: ring starts empty.
        compute_chunk<0,   64 >(xv, inv_l, buf[0], lane);  BAR_ARRIVE(FULL0);
        compute_chunk<64,  128>(xv, inv_l, buf[1], lane);  BAR_ARRIVE(FULL1);
        compute_chunk<128, 192>(xv, inv_l, buf[2], lane);  BAR_ARRIVE(FULL2);

        // Chunks 3..10: wait for buffer s%3 to drain (3 chunks of slack).
#define PSTEP(LO, HI, FREE_B, FULL_B, K)                         \
        BAR_SYNC(FREE_B);                                        \
        compute_chunk<LO, HI>(xv, inv_l, buf[K], lane);          \
        BAR_ARRIVE(FULL_B);

        PSTEP(192, 256, FREE0, FULL0, 0)
        PSTEP(256, 320, FREE1, FULL1, 1)
        PSTEP(320, 384, FREE2, FULL2, 2)
        PSTEP(384, 448, FREE0, FULL0, 0)
        PSTEP(448, 512, FREE1, FULL1, 1)
        PSTEP(512, 576, FREE2, FULL2, 2)
        PSTEP(576, 640, FREE0, FULL0, 0)
        PSTEP(640, 696, FREE1, FULL1, 1)
#undef PSTEP
    } else {
        // ---- Consumer warp: drain chunks 0..10. Uniform per-block policy:
        // pinned L2 partition for the first PERSIST_ROWS rows, streaming rest.
        if (wrow0 < PERSIST_ROWS)
            consumer_loop<true >(buf, out, wrow0, lane);
        else
            consumer_loop<false>(buf, out, wrow0, lane);
    }
}

extern "C" void kernel_launch(void* const* d_in, const int* in_sizes, int n_in,
                              void* d_out, int out_size) {
    const float* x   = (const float*)d_in[0];
    const float* lam = (const float*)d_in[1];
    float* out = (float*)d_out;

    int rows = in_sizes[0] / 16;             // 131072
    int grid = rows / ROWS_PER_BLOCK;        // 4096 blocks, 32 rows each
    dubois_kernel<<<grid, THREADS>>>(x, lam, out);
}

// round 15
// speedup vs baseline: 1.1433x; 1.1433x over previous
#include <cuda_runtime.h>

#define NCOLS            696     // 16 + 120 + 560
#define NQ_TOTAL         174     // NCOLS / 4
#define ROWS_PER_BLOCK   32      // one tile per block
#define THREADS          96      // warp 0 = producer, warps 1,2 = consumers
#define MIN_BLOCKS       4       // 4 blocks/SM: 4 producers + 8 store warps
#define ROW_STRIDE       68      // 64 data words + 4 pad (conflict-free STS.128 & LDS.128)
#define BUF_FLOATS       (ROWS_PER_BLOCK * ROW_STRIDE)  // 2176 floats = 8704 B
// smem: 3 buffers * 8704 B = 26,112 B static

// Named-barrier producer/consumer protocol (96 threads total).
// FULL[k]: producer arrives (32), consumers sync (64)  -> 96.
// FREE[k]: consumers arrive (64), producer syncs (32)  -> 96.
#define BAR_SYNC(ID)   asm volatile("bar.sync %0, 96;"   :: "r"(ID) : "memory")
#define BAR_ARRIVE(ID) asm volatile("bar.arrive %0, 96;" :: "r"(ID) : "memory")
#define FULL0 1
#define FULL1 2
#define FULL2 3
#define FREE0 4
#define FREE1 5
#define FREE2 6

// Dubois t-norm for a,b >= 0:  a*b / max(max(a,b), lambda) == min(a, b, a*b/lambda)
__device__ __forceinline__ float tnorm(float a, float b, float inv_l) {
    return fminf(fminf(a, b), a * b * inv_l);
}

// Pack values for columns [LO,HI) of this lane's row into its buffer row
// using STS.128 every 4 columns. col/rel are compile-time constants.
template<int LO, int HI>
__device__ __forceinline__ void compute_chunk(const float xv[16], float inv_l,
                                              float* __restrict__ wbuf, int lane) {
    float4 acc;
    float* rowp = wbuf + lane * ROW_STRIDE;

    int col = 0;
    #define EMIT(VAL)                                                           \
        do {                                                                    \
            if (col >= LO && col < HI) {                                        \
                int rel = col - LO;                                             \
                if ((rel & 3) == 0) acc.x = (VAL);                              \
                else if ((rel & 3) == 1) acc.y = (VAL);                         \
                else if ((rel & 3) == 2) acc.z = (VAL);                         \
                else {                                                          \
                    acc.w = (VAL);                                              \
                    *reinterpret_cast<float4*>(rowp + (rel - 3)) = acc;         \
                }                                                               \
            }                                                                   \
            col++;                                                              \
        } while (0)

    #pragma unroll
    for (int i = 0; i < 16; i++) EMIT(xv[i]);                    // singles 0..15

    #pragma unroll
    for (int i = 0; i < 16; i++) {                               // pairs 16..135
        #pragma unroll
        for (int j = i + 1; j < 16; j++) EMIT(tnorm(xv[i], xv[j], inv_l));
    }

    #pragma unroll
    for (int i = 0; i < 16; i++) {                               // triples 136..695
        #pragma unroll
        for (int j = i + 1; j < 16; j++) {
            float p = tnorm(xv[i], xv[j], inv_l);                // dead if no k in range
            #pragma unroll
            for (int k = j + 1; k < 16; k++) EMIT(tnorm(p, xv[k], inv_l));
        }
    }
    #undef EMIT
}

// One consumer warp's half of the writeout of columns [LO,HI) for the tile's
// 32 rows. CID selects which half of the quad-iterations this warp covers.
// LDS.128 conflict-free, STG.128 .cs coalesced.
template<int LO, int HI>
__device__ __forceinline__ void writeout_half(const float* __restrict__ wbuf,
                                              float4* __restrict__ out4,
                                              int wrow0, int lane, int cid) {
    constexpr int NQ = (HI - LO) / 4;    // 16 or 14 float4s per row
    constexpr int NH = NQ / 2;           // 8 or 7 iterations per consumer
    #pragma unroll
    for (int h = 0; h < NH; h++) {
        int it = cid * NH + h;
        int idx = it * 32 + lane;
        int q = idx % NQ;                // quad within chunk (fast with lane)
        int r = idx / NQ;                // row within the 32-row tile
        float4 v = *reinterpret_cast<const float4*>(wbuf + r * ROW_STRIDE + 4 * q);
        __stcs(&out4[(size_t)(wrow0 + r) * NQ_TOTAL + (LO / 4) + q], v);
    }
}

__global__ void __launch_bounds__(THREADS, MIN_BLOCKS)
dubois_kernel(const float* __restrict__ x,
              const float* __restrict__ lambda_,
              float* __restrict__ out) {
    __shared__ float buf[3][BUF_FLOATS];   // 26,112 B: 3-deep ring

    const int lane = threadIdx.x & 31;
    const int wid  = threadIdx.x >> 5;

    const int wrow0 = blockIdx.x * ROWS_PER_BLOCK;
    float4* out4 = reinterpret_cast<float4*>(out);

    if (wid == 0) {
        // ---- Producer warp ----
        const float inv_l = 1.0f / __ldg(lambda_);
        const int row = wrow0 + lane;
        float xv[16];
        const float4* xp = reinterpret_cast<const float4*>(x) + (size_t)row * 4;
        float4 a = xp[0], b = xp[1], c = xp[2], d = xp[3];
        xv[0]=a.x;  xv[1]=a.y;  xv[2]=a.z;  xv[3]=a.w;
        xv[4]=b.x;  xv[5]=b.y;  xv[6]=b.z;  xv[7]=b.w;
        xv[8]=c.x;  xv[9]=c.y;  xv[10]=c.z; xv[11]=c.w;
        xv[12]=d.x; xv[13]=d.y; xv[14]=d.z; xv[15]=d.w;

        // Chunks 0..2: ring starts empty.
        compute_chunk<0,   64 >(xv, inv_l, buf[0], lane);  BAR_ARRIVE(FULL0);
        compute_chunk<64,  128>(xv, inv_l, buf[1], lane);  BAR_ARRIVE(FULL1);
        compute_chunk<128, 192>(xv, inv_l, buf[2], lane);  BAR_ARRIVE(FULL2);

        // Chunks 3..10: wait for buffer s%3 to drain (3 chunks of slack).
#define PSTEP(LO, HI, FREE_B, FULL_B, K)                         \
        BAR_SYNC(FREE_B);                                        \
        compute_chunk<LO, HI>(xv, inv_l, buf[K], lane);          \
        BAR_ARRIVE(FULL_B);

        PSTEP(192, 256, FREE0, FULL0, 0)
        PSTEP(256, 320, FREE1, FULL1, 1)
        PSTEP(320, 384, FREE2, FULL2, 2)
        PSTEP(384, 448, FREE0, FULL0, 0)
        PSTEP(448, 512, FREE1, FULL1, 1)
        PSTEP(512, 576, FREE2, FULL2, 2)
        PSTEP(576, 640, FREE0, FULL0, 0)
        PSTEP(640, 696, FREE1, FULL1, 1)
#undef PSTEP
    } else {
        // ---- Consumer warps (2): split each chunk's writeout in half. ----
        const int cid = wid - 1;   // 0 or 1

#define CSTEP(LO, HI, FULL_B, K)                                           \
        BAR_SYNC(FULL_B);                                                  \
        writeout_half<LO, HI>(buf[K], out4, wrow0, lane, cid);

        CSTEP(0,   64,  FULL0, 0)  BAR_ARRIVE(FREE0);
        CSTEP(64,  128, FULL1, 1)  BAR_ARRIVE(FREE1);
        CSTEP(128, 192, FULL2, 2)  BAR_ARRIVE(FREE2);
        CSTEP(192, 256, FULL0, 0)  BAR_ARRIVE(FREE0);
        CSTEP(256, 320, FULL1, 1)  BAR_ARRIVE(FREE1);
        CSTEP(320, 384, FULL2, 2)  BAR_ARRIVE(FREE2);
        CSTEP(384, 448, FULL0, 0)  BAR_ARRIVE(FREE0);
        CSTEP(448, 512, FULL1, 1)  BAR_ARRIVE(FREE1);
        CSTEP(512, 576, FULL2, 2)
        CSTEP(576, 640, FULL0, 0)
        CSTEP(640, 696, FULL1, 1)
#undef CSTEP
    }
}

extern "C" void kernel_launch(void* const* d_in, const int* in_sizes, int n_in,
                              void* d_out, int out_size) {
    const float* x   = (const float*)d_in[0];
    const float* lam = (const float*)d_in[1];
    float* out = (float*)d_out;

    int rows = in_sizes[0] / 16;             // 131072
    int grid = rows / ROWS_PER_BLOCK;        // 4096 blocks, 32 rows each
    dubois_kernel<<<grid, THREADS>>>(x, lam, out);
}